// round 11
// baseline (speedup 1.0000x reference)
#include <cuda_runtime.h>
#include <cuda_bf16.h>
#include <cstdint>

// R10: persistent grid-stride version of the champion (R7/R8 ~30.8us).
// Rationale: steady-state DRAM time is 176MB/6.27TB/s ~= 28.1us; the ~2.7us
// residual is block-retire/wave-transition churn (6.6 waves of one-shot
// blocks, each draining its memory pipeline at retire). A persistent grid
// (148 SMs x 8 blocks) loops over chunks and keeps the pipeline primed.
//
// Established L2 plan: z streamed with __ldcs (protects dir/out residency
// across graph replays), dir/out with evict_last hints. Never pin z.
// z_3 remains unread (reference discards c_3).

constexpr int TPB  = 256;
constexpr int ROWS = 256;                              // rows per chunk
constexpr int WORDS_PER_CHUNK = ROWS * 11;             // 2816 floats
constexpr int F4_PER_CHUNK    = WORDS_PER_CHUNK / 4;   // 704
constexpr int SMS = 148;
constexpr int BLOCKS_PER_SM = 8;                        // 23KB smem -> 8/SM fits

__device__ __forceinline__ uint64_t policy_last() {
    uint64_t p;
    asm("createpolicy.fractional.L2::evict_last.b64 %0, 1.0;" : "=l"(p));
    return p;
}
__device__ __forceinline__ float4 ldg_f4_last(const float4* p, uint64_t pol) {
    float4 v;
    asm("ld.global.nc.L2::cache_hint.v4.f32 {%0,%1,%2,%3}, [%4], %5;"
        : "=f"(v.x), "=f"(v.y), "=f"(v.z), "=f"(v.w) : "l"(p), "l"(pol));
    return v;
}
__device__ __forceinline__ void stg_f32_last(float* p, float v, uint64_t pol) {
    asm volatile("st.global.L2::cache_hint.f32 [%0], %1, %2;"
                 :: "l"(p), "f"(v), "l"(pol) : "memory");
}

__global__ __launch_bounds__(TPB, BLOCKS_PER_SM)
void yolo_zone_kernel(const float4* __restrict__ z1v,
                      const float4* __restrict__ z2v,
                      const float4* __restrict__ dir,
                      float* __restrict__ out,
                      int n, long nf4, int nchunks)
{
    __shared__ float s1[WORDS_PER_CHUNK];
    __shared__ float s2[WORDS_PER_CHUNK];

    const int t = threadIdx.x;
    const uint64_t pol_last = policy_last();

    for (int chunk = blockIdx.x; chunk < nchunks; chunk += gridDim.x) {
        const long base4 = (long)chunk * F4_PER_CHUNK;

        // Stage z1/z2: 704 float4 each, 256 threads -> 3 iters (last partial).
        #pragma unroll
        for (int k = 0; k < 3; k++) {
            int  sidx = t + k * TPB;
            long g    = base4 + sidx;
            if (sidx < F4_PER_CHUNK && g < nf4) {
                reinterpret_cast<float4*>(s1)[sidx] = __ldcs(z1v + g);
                reinterpret_cast<float4*>(s2)[sidx] = __ldcs(z2v + g);
            }
        }

        // dir: coalesced float4/row; overlaps with staging latency.
        const int row = chunk * ROWS + t;
        float4 d = make_float4(0.f, 0.f, 0.f, 0.f);
        if (row < n) d = ldg_f4_last(dir + row, pol_last);

        __syncthreads();

        if (row < n) {
            const int w = t * 11;   // 11 coprime with 32 -> conflict-free LDS
            float a0 = s1[w + 0], a1 = s1[w + 1], a2 = s1[w + 2], a3 = s1[w + 3];
            float b0 = s2[w + 0], b1 = s2[w + 1], b2 = s2[w + 2], b3 = s2[w + 3];

            // Centers and direction vector (division by 2 exact in fp32).
            float dx = (b0 + b2) * 0.5f - (a0 + a2) * 0.5f;
            float dy = -((b1 + b3) * 0.5f - (a1 + a3) * 0.5f);

            // degrees(atan2), truncate toward zero (matches .astype(int32)).
            float phi = atan2f(dy, dx) * 57.29577951308232f;
            int phi_long = (int)phi;

            // python-style mod 360 of (90 - phi_long); [-90,270] -> one fixup.
            int m = 90 - phi_long;
            if (m < 0) m += 360;
            if (m >= 360) m -= 360;

            // zone = floor((m + 45) / 90) mod 4
            int zone = ((m + 45) / 90) & 3;

            float r = (zone == 0) ? d.x : (zone == 1) ? d.y
                    : (zone == 2) ? d.z : d.w;
            stg_f32_last(out + row, r, pol_last);
        }

        // Protect smem before next chunk's staging overwrites it.
        __syncthreads();
    }
}

extern "C" void kernel_launch(void* const* d_in, const int* in_sizes, int n_in,
                              void* d_out, int out_size)
{
    const float4* z1v = (const float4*)d_in[0];
    const float4* z2v = (const float4*)d_in[1];
    // d_in[2] (z_3) intentionally unused — reference discards c_3.
    const float4* dir = (const float4*)d_in[3];
    float*        out = (float*)d_out;

    int  n       = out_size;
    long nf4     = ((long)n * 11) / 4;            // exact: 2e6*11 divisible by 4
    int  nchunks = (n + ROWS - 1) / ROWS;         // 7813

    int grid = SMS * BLOCKS_PER_SM;               // 1184 persistent blocks
    if (grid > nchunks) grid = nchunks;
    yolo_zone_kernel<<<grid, TPB>>>(z1v, z2v, dir, out, n, nf4, nchunks);
}

// round 12
// speedup vs baseline: 1.0688x; 1.0688x over previous
#include <cuda_runtime.h>
#include <cuda_bf16.h>
#include <cstdint>

// R11 = R7 champion with warp-autonomous staging: each warp stages exactly
// the smem slice it consumes (32 rows * 44 B = 1408 B = 88 float4, 16B-aligned
// base), so block-wide __syncthreads is replaced by __syncwarp. No warp ever
// waits on another warp's DRAM latency; DRAM request pattern is unchanged.
//
// Established L2 plan (R2..R10):
//   z1/z2 : __ldcs streaming (protects dir/out L2 residency across replays)
//   dir   : evict_last hint load   (32 MB, reused every replay)
//   out   : evict_last hint store  (8 MB, rewritten every replay)
//   never pin z (R6 regression, R8 null); no persistent grid (R10 regression).
// z_3 remains unread (reference discards c_3).

constexpr int TPB  = 256;
constexpr int ROWS = 256;
constexpr int WORDS_PER_BLOCK = ROWS * 11;       // 2816 floats
constexpr int F4_PER_WARP     = 32 * 11 / 4;     // 88 float4 per warp slice
constexpr int WORDS_PER_WARP  = 32 * 11;         // 352

__device__ __forceinline__ uint64_t policy_last() {
    uint64_t p;
    asm("createpolicy.fractional.L2::evict_last.b64 %0, 1.0;" : "=l"(p));
    return p;
}
__device__ __forceinline__ float4 ldg_f4_last(const float4* p, uint64_t pol) {
    float4 v;
    asm("ld.global.nc.L2::cache_hint.v4.f32 {%0,%1,%2,%3}, [%4], %5;"
        : "=f"(v.x), "=f"(v.y), "=f"(v.z), "=f"(v.w) : "l"(p), "l"(pol));
    return v;
}
__device__ __forceinline__ void stg_f32_last(float* p, float v, uint64_t pol) {
    asm volatile("st.global.L2::cache_hint.f32 [%0], %1, %2;"
                 :: "l"(p), "f"(v), "l"(pol) : "memory");
}

__global__ __launch_bounds__(TPB)
void yolo_zone_kernel(const float4* __restrict__ z1v,
                      const float4* __restrict__ z2v,
                      const float4* __restrict__ dir,
                      float* __restrict__ out,
                      int n, long nf4)
{
    __shared__ float s1[WORDS_PER_BLOCK];
    __shared__ float s2[WORDS_PER_BLOCK];

    const int t    = threadIdx.x;
    const int wid  = t >> 5;
    const int lane = t & 31;

    // Warp-private slice: rows [blk*256 + wid*32, +32) -> 88 float4.
    const long warp_base4 = (long)blockIdx.x * (WORDS_PER_BLOCK / 4)
                          + (long)wid * F4_PER_WARP;
    float4* s1w = reinterpret_cast<float4*>(s1 + wid * WORDS_PER_WARP);
    float4* s2w = reinterpret_cast<float4*>(s2 + wid * WORDS_PER_WARP);

    // Stage 88 float4 per array with 32 lanes: k=0,1 full, k=2 partial (24).
    #pragma unroll
    for (int k = 0; k < 3; k++) {
        int  sidx = lane + k * 32;
        long g    = warp_base4 + sidx;
        if (sidx < F4_PER_WARP && g < nf4) {
            s1w[sidx] = __ldcs(z1v + g);
            s2w[sidx] = __ldcs(z2v + g);
        }
    }

    // dir: coalesced float4/row; overlaps staging latency.
    const int row = blockIdx.x * ROWS + t;
    const uint64_t pol_last = policy_last();
    float4 d = make_float4(0.f, 0.f, 0.f, 0.f);
    if (row < n) d = ldg_f4_last(dir + row, pol_last);

    __syncwarp();          // only this warp's own loads must be visible
    if (row >= n) return;

    const int w = wid * WORDS_PER_WARP + lane * 11;  // conflict-free (11 ⊥ 32)
    float a0 = s1[w + 0], a1 = s1[w + 1], a2 = s1[w + 2], a3 = s1[w + 3];
    float b0 = s2[w + 0], b1 = s2[w + 1], b2 = s2[w + 2], b3 = s2[w + 3];

    // Centers and direction vector (division by 2 exact in fp32).
    float dx = (b0 + b2) * 0.5f - (a0 + a2) * 0.5f;
    float dy = -((b1 + b3) * 0.5f - (a1 + a3) * 0.5f);

    // degrees(atan2), truncate toward zero (matches .astype(int32)).
    float phi = atan2f(dy, dx) * 57.29577951308232f;
    int phi_long = (int)phi;

    // python-style mod 360 of (90 - phi_long); range [-90, 270] -> one fixup.
    int m = 90 - phi_long;
    if (m < 0) m += 360;
    if (m >= 360) m -= 360;

    // zone = floor((m + 45) / 90) mod 4
    int zone = ((m + 45) / 90) & 3;

    float r = (zone == 0) ? d.x : (zone == 1) ? d.y : (zone == 2) ? d.z : d.w;
    stg_f32_last(out + row, r, pol_last);
}

extern "C" void kernel_launch(void* const* d_in, const int* in_sizes, int n_in,
                              void* d_out, int out_size)
{
    const float4* z1v = (const float4*)d_in[0];
    const float4* z2v = (const float4*)d_in[1];
    // d_in[2] (z_3) intentionally unused — reference discards c_3.
    const float4* dir = (const float4*)d_in[3];
    float*        out = (float*)d_out;

    int  n   = out_size;
    long nf4 = ((long)n * 11) / 4;   // exact: 2e6*11 divisible by 4

    int grid = (n + ROWS - 1) / ROWS;
    yolo_zone_kernel<<<grid, TPB>>>(z1v, z2v, dir, out, n, nf4);
}